// round 12
// baseline (speedup 1.0000x reference)
#include <cuda_runtime.h>
#include <cstdint>

#define H 1024
#define L 50
#define V 50257
#define NBLK ((V + 7) / 8)    // 6283 blocks for the big matvec
#define GRID 592              // 4 CTAs x 148 SMs: all resident (spin-barrier safe)
#define NW (GRID * 8)         // 4736 warps

// ---------------- scratch (device globals; no allocation allowed) ----------
__device__ unsigned g_bar[8];
__device__ unsigned g_ticket;
__device__ float g_sink;

__device__ float g_scores[L];
__device__ float g_cat2[2 * H];   // [embedded | attn_applied]
__device__ float g_cp[2 * H];     // comb half-row partials
__device__ float g_x0[H];         // relu(comb)  = cell-0 input
__device__ float g_x1[H];         // relu(h1)    = cell-1 input
__device__ float g_h1[H];
__device__ float g_h2[H];
__device__ float g_dp[6 * H];     // gate dots [c][i], c = 2*gate + (ih:0 / hh:1)
__device__ float g_pm[NBLK + 64];
__device__ float g_ps[NBLK + 64];
__device__ float g_lse;

__device__ __forceinline__ float dot4(float4 a, float4 b) {
    return a.x * b.x + a.y * b.y + a.z * b.z + a.w * b.w;
}
__device__ __forceinline__ float wred(float a) {
    #pragma unroll
    for (int o = 16; o; o >>= 1) a += __shfl_down_sync(0xffffffffu, a, o);
    return a;
}
__device__ __forceinline__ void gbar(int ph) {
    __threadfence();
    __syncthreads();
    if (threadIdx.x == 0) {
        atomicAdd(&g_bar[ph], 1u);
        while (*((volatile unsigned*)&g_bar[ph]) < GRID) __nanosleep(32);
    }
    __syncthreads();
}

// ---------------- K-1: reset barrier state (graph-replay safe) -------------
__global__ void k_reset() {
    if (threadIdx.x < 8) g_bar[threadIdx.x] = 0u;
    if (threadIdx.x == 8) g_ticket = 0u;
}

// ---------------- K0: fused front-end megakernel ---------------------------
__global__ void __launch_bounds__(256, 4)
k_front(const int* __restrict__ ids, const float* __restrict__ hidden,
        const float* __restrict__ enc, const float* __restrict__ emb,
        const float* __restrict__ attn_w, const float* __restrict__ attn_b,
        const float* __restrict__ comb_w, const float* __restrict__ comb_b,
        const float* __restrict__ w_ih, const float* __restrict__ w_hh,
        const float* __restrict__ b_ih, const float* __restrict__ b_hh,
        float* __restrict__ out)
{
    __shared__ float s_aw[64];
    int warp = threadIdx.x >> 5, lane = threadIdx.x & 31;
    int gw = blockIdx.x * 8 + warp;

    // ======== P0: scores | h-side gates0 (w_hh@h0) | prefetch w_ih ========
    if (gw < 50) {
        const float4* ef = (const float4*)(emb + (size_t)ids[0] * H);
        const float4* hf = (const float4*)hidden;
        const float4* wf = (const float4*)(attn_w + (size_t)gw * 2 * H);
        float acc = 0.f;
        #pragma unroll
        for (int k = 0; k < 8; k++) acc += dot4(wf[lane + k * 32], ef[lane + k * 32]);
        #pragma unroll
        for (int k = 0; k < 8; k++) acc += dot4(wf[256 + lane + k * 32], hf[lane + k * 32]);
        acc = wred(acc);
        if (lane == 0) g_scores[gw] = acc + attn_b[gw];
    } else if (gw >= 56 && gw < 64) {
        const float4* ef = (const float4*)(emb + (size_t)ids[0] * H);
        int i4 = (gw - 56) * 32 + lane;
        ((float4*)g_cat2)[i4] = ef[i4];                 // embedded half of concat
    } else if (gw >= 64 && gw < 64 + 3072) {
        int u = gw - 64;
        int cidx = u >> 10, i = u & (H - 1);            // gate row, hh side
        const float4* wf = (const float4*)(w_hh + (size_t)(cidx * H + i) * H);
        const float4* hf = (const float4*)hidden;
        float acc = 0.f;
        #pragma unroll
        for (int k = 0; k < 8; k++) acc += dot4(wf[lane + k * 32], hf[lane + k * 32]);
        acc = wred(acc);
        if (lane == 0) g_dp[(2 * cidx + 1) * H + i] = acc;
    } else if (gw >= 3136) {
        // prefetch w_ih (3072 rows x 4 KB) into L2
        float s = 0.f;
        for (int rr = 0; rr < 2; rr++) {
            int r = (gw - 3136) * 2 + rr;
            if (r < 3072) {
                const float4* p = (const float4*)(w_ih + (size_t)r * H);
                #pragma unroll
                for (int k = 0; k < 8; k++) {
                    float4 a = __ldcg(p + lane + k * 32);
                    s += a.x + a.y + a.z + a.w;
                }
            }
        }
        if (__float_as_uint(s) == 0xdeadbeefu) g_sink = s;   // keep loads alive
    }
    gbar(0);

    // ======== P1: softmax (redundant per block) + attn_applied ========
    if (blockIdx.x < 8) {
        int t = threadIdx.x;
        if (t < 64) s_aw[t] = (t < L) ? __ldcg(&g_scores[t]) : -1e30f;
        __syncthreads();
        if (t < 32) {
            float a = s_aw[t], b = s_aw[t + 32];
            float m = fmaxf(a, b);
            #pragma unroll
            for (int o = 16; o; o >>= 1) m = fmaxf(m, __shfl_xor_sync(0xffffffffu, m, o));
            float e1 = (t < L) ? __expf(a - m) : 0.f;
            float e2 = (t + 32 < L) ? __expf(b - m) : 0.f;
            float s = e1 + e2;
            #pragma unroll
            for (int o = 16; o; o >>= 1) s += __shfl_xor_sync(0xffffffffu, s, o);
            float inv = 1.f / s;
            s_aw[t] = e1 * inv;
            s_aw[t + 32] = e2 * inv;
        }
        __syncthreads();
        if (blockIdx.x == 0 && t < L) out[V + H + t] = s_aw[t];   // attn_weights
        if (t < 128) {
            int i = blockIdx.x * 128 + t;
            float acc = 0.f;
            #pragma unroll 10
            for (int l = 0; l < L; l++) acc += s_aw[l] * enc[l * H + i];
            g_cat2[H + i] = acc;
        }
    }
    gbar(1);

    // ======== P2: comb matvec (2048 half-row units) ========
    if (gw < 2048) {
        int row = gw >> 1, half = gw & 1;
        const float4* wf = (const float4*)(comb_w + (size_t)row * 2 * H + half * H);
        const float4* vf = (const float4*)(g_cat2 + half * H);
        float acc = 0.f;
        #pragma unroll
        for (int k = 0; k < 8; k++) acc += dot4(wf[lane + k * 32], vf[lane + k * 32]);
        acc = wred(acc);
        if (lane == 0) g_cp[gw] = acc;
    }
    gbar(2);

    // ======== P3: comb halves + bias + relu -> g_x0 ========
    if (gw < 32) {
        int i = gw * 32 + lane;
        float v = __ldcg(&g_cp[2 * i]) + __ldcg(&g_cp[2 * i + 1]) + comb_b[i];
        g_x0[i] = fmaxf(v, 0.f);
    }
    gbar(3);

    // ======== P4: x-side gates0 (w_ih@x0, L2-hot from prefetch) ========
    if (gw < 3072) {
        int cidx = gw >> 10, i = gw & (H - 1);
        const float4* wf = (const float4*)(w_ih + (size_t)(cidx * H + i) * H);
        const float4* vf = (const float4*)g_x0;
        float acc = 0.f;
        #pragma unroll
        for (int k = 0; k < 8; k++) acc += dot4(wf[lane + k * 32], vf[lane + k * 32]);
        acc = wred(acc);
        if (lane == 0) g_dp[(2 * cidx) * H + i] = acc;
    }
    gbar(4);

    // ======== P5: GRU combine cell 0 -> g_h1, g_x1 ========
    if (gw < 32) {
        int i = gw * 32 + lane;
        float d0 = __ldcg(&g_dp[0 * H + i]) + b_ih[i];
        float d1 = __ldcg(&g_dp[1 * H + i]) + b_hh[i];
        float d2 = __ldcg(&g_dp[2 * H + i]) + b_ih[H + i];
        float d3 = __ldcg(&g_dp[3 * H + i]) + b_hh[H + i];
        float d4 = __ldcg(&g_dp[4 * H + i]) + b_ih[2 * H + i];
        float d5 = __ldcg(&g_dp[5 * H + i]) + b_hh[2 * H + i];
        float r = 1.f / (1.f + __expf(-(d0 + d1)));
        float z = 1.f / (1.f + __expf(-(d2 + d3)));
        float n = tanhf(d4 + r * d5);
        float h = (1.f - z) * n + z * hidden[i];
        g_h1[i] = h;
        g_x1[i] = fmaxf(h, 0.f);
    }
    gbar(5);

    // ======== P6: gates cell 1 (6144 units, all L2-hot) ========
    #pragma unroll
    for (int rep = 0; rep < 2; rep++) {
        int u = gw + rep * NW;
        if (u < 6144) {
            int c = u >> 10, i = u & (H - 1);
            int gate = c >> 1;
            const float* wm = (c & 1) ? w_hh : w_ih;
            const float4* wf = (const float4*)(wm + (size_t)(gate * H + i) * H);
            const float4* vf = (const float4*)((c & 1) ? g_h1 : g_x1);
            float acc = 0.f;
            #pragma unroll
            for (int k = 0; k < 8; k++) acc += dot4(wf[lane + k * 32], vf[lane + k * 32]);
            acc = wred(acc);
            if (lane == 0) g_dp[c * H + i] = acc;
        }
    }
    gbar(6);

    // ======== P7: GRU combine cell 1 -> g_h2, hidden output ========
    if (gw < 32) {
        int i = gw * 32 + lane;
        float d0 = __ldcg(&g_dp[0 * H + i]) + b_ih[i];
        float d1 = __ldcg(&g_dp[1 * H + i]) + b_hh[i];
        float d2 = __ldcg(&g_dp[2 * H + i]) + b_ih[H + i];
        float d3 = __ldcg(&g_dp[3 * H + i]) + b_hh[H + i];
        float d4 = __ldcg(&g_dp[4 * H + i]) + b_ih[2 * H + i];
        float d5 = __ldcg(&g_dp[5 * H + i]) + b_hh[2 * H + i];
        float r = 1.f / (1.f + __expf(-(d0 + d1)));
        float z = 1.f / (1.f + __expf(-(d2 + d3)));
        float n = tanhf(d4 + r * d5);
        float h = (1.f - z) * n + z * g_h1[i];
        g_h2[i] = h;
        out[V + i] = h;
    }
}

// ---------------- K1: big matvec out_w @ h2 + fused lse --------------------
__global__ void __launch_bounds__(256)
k_out(const float* __restrict__ out_w,
      const float* __restrict__ out_b,
      float* __restrict__ out) {
    __shared__ float sm[8];
    __shared__ unsigned s_tick;
    int warp = threadIdx.x >> 5, lane = threadIdx.x & 31;
    int row = blockIdx.x * 8 + warp;
    float logit = -1e30f;
    if (row < V) {
        const float4* w = (const float4*)(out_w + (size_t)row * H);
        const float4* v = (const float4*)g_h2;
        float acc = 0.f;
        #pragma unroll
        for (int k = 0; k < 8; k++) {
            int m = lane + k * 32;
            float4 a = __ldcs(w + m);   // stream weights
            float4 b = v[m];            // L1-resident vector
            acc += dot4(a, b);
        }
        acc = wred(acc);
        if (lane == 0) {
            logit = acc + out_b[row];
            out[row] = logit;
        }
    }
    if (lane == 0) sm[warp] = logit;
    __syncthreads();
    if (threadIdx.x == 0) {
        float m = -1e30f;
        #pragma unroll
        for (int k = 0; k < 8; k++) m = fmaxf(m, sm[k]);
        float s = 0.f;
        #pragma unroll
        for (int k = 0; k < 8; k++) s += __expf(sm[k] - m);
        g_pm[blockIdx.x] = m;
        g_ps[blockIdx.x] = s;
    }
    // last-done block reduces partials -> g_lse
    __threadfence();
    __syncthreads();
    if (threadIdx.x == 0) s_tick = atomicAdd(&g_ticket, 1u);
    __syncthreads();
    if (s_tick == NBLK - 1) {
        int t = threadIdx.x;
        float m = -1e30f, s = 0.f;
        for (int b = t; b < NBLK; b += 256) {
            float bm = __ldcg(&g_pm[b]), bs = __ldcg(&g_ps[b]);
            if (bm > m) { s = s * __expf(m - bm) + bs; m = bm; }
            else        { s += bs * __expf(bm - m); }
        }
        __shared__ float rm[8], rs[8];
        #pragma unroll
        for (int o = 16; o; o >>= 1) {
            float om = __shfl_xor_sync(0xffffffffu, m, o);
            float os = __shfl_xor_sync(0xffffffffu, s, o);
            float M = fmaxf(m, om);
            s = s * __expf(m - M) + os * __expf(om - M);
            m = M;
        }
        if ((t & 31) == 0) { rm[t >> 5] = m; rs[t >> 5] = s; }
        __syncthreads();
        if (t < 8) {
            m = rm[t]; s = rs[t];
            #pragma unroll
            for (int o = 4; o; o >>= 1) {
                float om = __shfl_xor_sync(0xffu, m, o);
                float os = __shfl_xor_sync(0xffu, s, o);
                float M = fmaxf(m, om);
                s = s * __expf(m - M) + os * __expf(om - M);
                m = M;
            }
            if (t == 0) g_lse = m + logf(s);
        }
    }
}

// ---------------- K2: normalize log-probs ----------------------------------
__global__ void __launch_bounds__(256)
k_norm(float* __restrict__ out) {
    int v = blockIdx.x * blockDim.x + threadIdx.x;
    if (v < V) out[v] -= g_lse;
}

// ---------------- launch ----------------------------------------------------
extern "C" void kernel_launch(void* const* d_in, const int* in_sizes, int n_in,
                              void* d_out, int out_size) {
    const int*   ids     = (const int*)d_in[0];
    const float* hidden  = (const float*)d_in[1];
    const float* enc     = (const float*)d_in[2];
    const float* emb     = (const float*)d_in[3];
    const float* attn_w  = (const float*)d_in[4];
    const float* attn_b  = (const float*)d_in[5];
    const float* comb_w  = (const float*)d_in[6];
    const float* comb_b  = (const float*)d_in[7];
    const float* w_ih    = (const float*)d_in[8];
    const float* w_hh    = (const float*)d_in[9];
    const float* b_ih    = (const float*)d_in[10];
    const float* b_hh    = (const float*)d_in[11];
    const float* out_w   = (const float*)d_in[12];
    const float* out_b   = (const float*)d_in[13];
    float* out = (float*)d_out;

    k_reset<<<1, 32>>>();
    k_front<<<GRID, 256>>>(ids, hidden, enc, emb, attn_w, attn_b,
                           comb_w, comb_b, w_ih, w_hh, b_ih, b_hh, out);
    k_out<<<NBLK, 256>>>(out_w, out_b, out);
    k_norm<<<(V + 255) / 256, 256>>>(out);
}

// round 13
// speedup vs baseline: 1.0472x; 1.0472x over previous
#include <cuda_runtime.h>
#include <cstdint>

#define H 1024
#define L 50
#define V 50257
#define NBLK ((V + 7) / 8)   // 6283 blocks for the big matvec

// ---------------- scratch (device globals; no allocation allowed) ----------
__device__ unsigned g_t0, g_t1, g_t2;   // exit tickets
__device__ float g_scores[L];
__device__ float g_cat2[2 * H];   // [embedded | attn_applied]
__device__ float g_x0[H];         // relu(comb)  = cell-0 input
__device__ float g_x1[H];         // relu(h1)    = cell-1 input
__device__ float g_h1[H];
__device__ float g_h2[H];
__device__ float g_dp[6 * H];     // gate dots [c][i], c = 2*gate + (0:ih, 1:hh)
__device__ float g_pm[NBLK + 64];
__device__ float g_ps[NBLK + 64];
__device__ float g_lse;

__device__ __forceinline__ float dot4(float4 a, float4 b) {
    return a.x * b.x + a.y * b.y + a.z * b.z + a.w * b.w;
}
__device__ __forceinline__ float wred(float a) {
    #pragma unroll
    for (int o = 16; o; o >>= 1) a += __shfl_down_sync(0xffffffffu, a, o);
    return a;
}

// GRU nonlinearity for element i (d* already include biases)
__device__ __forceinline__ float gru_elem(float d0, float d1, float d2,
                                          float d3, float d4, float d5,
                                          float hold) {
    float r = 1.f / (1.f + __expf(-(d0 + d1)));
    float z = 1.f / (1.f + __expf(-(d2 + d3)));
    float n = tanhf(d4 + r * d5);
    return (1.f - z) * n + z * hold;
}

// ---------------- K-1: reset tickets (graph-replay safe) -------------------
__global__ void k_reset() {
    g_t0 = 0u; g_t1 = 0u; g_t2 = 0u;
}

// ---------------- K0: scores + emb copy + hh-side cell-0 gates -------------
// grid 392 x 256. gw<50: attention scores. gw in [56,64): copy emb->cat2.
// gw>=64: w_hh @ hidden for all 3 gates (no dependency on attention!).
__global__ void __launch_bounds__(256)
k_scores_hh(const int* __restrict__ ids, const float* __restrict__ hidden,
            const float* __restrict__ emb,
            const float* __restrict__ attn_w, const float* __restrict__ attn_b,
            const float* __restrict__ w_hh) {
    int warp = threadIdx.x >> 5, lane = threadIdx.x & 31;
    int gw = blockIdx.x * 8 + warp;

    if (gw < 50) {
        const float4* ef = (const float4*)(emb + (size_t)ids[0] * H);
        const float4* hf = (const float4*)hidden;
        const float4* wf = (const float4*)(attn_w + (size_t)gw * 2 * H);
        float acc = 0.f;
        #pragma unroll
        for (int k = 0; k < 8; k++) acc += dot4(wf[lane + k * 32], ef[lane + k * 32]);
        #pragma unroll
        for (int k = 0; k < 8; k++) acc += dot4(wf[256 + lane + k * 32], hf[lane + k * 32]);
        acc = wred(acc);
        if (lane == 0) g_scores[gw] = acc + attn_b[gw];
    } else if (gw >= 56 && gw < 64) {
        const float4* ef = (const float4*)(emb + (size_t)ids[0] * H);
        int i4 = (gw - 56) * 32 + lane;
        ((float4*)g_cat2)[i4] = ef[i4];
    } else if (gw >= 64) {
        int u = gw - 64;                      // 0..3071
        int gate = u >> 10, i = u & (H - 1);
        const float4* wf = (const float4*)(w_hh + (size_t)(gate * H + i) * H);
        const float4* hf = (const float4*)hidden;
        float acc = 0.f;
        #pragma unroll
        for (int k = 0; k < 8; k++) acc += dot4(wf[lane + k * 32], hf[lane + k * 32]);
        acc = wred(acc);
        if (lane == 0) g_dp[(2 * gate + 1) * H + i] = acc;
    }
}

// ---------------- K1: softmax + attn_applied (8 blocks) --------------------
__global__ void __launch_bounds__(128)
k_attn(const float* __restrict__ enc, float* __restrict__ out) {
    __shared__ float aw[64];
    int t = threadIdx.x;
    if (t < 64) aw[t] = (t < L) ? g_scores[t] : -1e30f;
    __syncthreads();
    if (t < 32) {
        float a = aw[t], b = aw[t + 32];
        float m = fmaxf(a, b);
        #pragma unroll
        for (int o = 16; o; o >>= 1) m = fmaxf(m, __shfl_xor_sync(0xffffffffu, m, o));
        float e1 = (t < L) ? __expf(a - m) : 0.f;
        float e2 = (t + 32 < L) ? __expf(b - m) : 0.f;
        float s = e1 + e2;
        #pragma unroll
        for (int o = 16; o; o >>= 1) s += __shfl_xor_sync(0xffffffffu, s, o);
        float inv = 1.f / s;
        aw[t] = e1 * inv;
        aw[t + 32] = e2 * inv;
    }
    __syncthreads();
    if (blockIdx.x == 0 && t < L) out[V + H + t] = aw[t];   // attn_weights
    int i = blockIdx.x * 128 + t;
    float acc = 0.f;
    #pragma unroll 10
    for (int l = 0; l < L; l++) acc += aw[l] * enc[l * H + i];
    g_cat2[H + i] = acc;
}

// ---------------- K2: comb matvec -> relu -> g_x0 --------------------------
__global__ void __launch_bounds__(256)
k_comb(const float* __restrict__ comb_w, const float* __restrict__ comb_b) {
    __shared__ float sc[2 * H];
    __shared__ float part[8];
    for (int i = threadIdx.x; i < 2 * H; i += 256) sc[i] = g_cat2[i];
    __syncthreads();
    int warp = threadIdx.x >> 5, lane = threadIdx.x & 31;
    int row = blockIdx.x * 4 + (warp >> 1);
    int half = warp & 1;
    const float4* w = (const float4*)(comb_w + (size_t)row * 2 * H + half * H);
    float acc = 0.f;
    #pragma unroll
    for (int k = 0; k < 8; k++) {
        int m = lane + k * 32;
        float4 a = w[m];
        int j = half * H + m * 4;
        acc += a.x * sc[j] + a.y * sc[j + 1] + a.z * sc[j + 2] + a.w * sc[j + 3];
    }
    acc = wred(acc);
    if (lane == 0) part[warp] = acc;
    __syncthreads();
    if (threadIdx.x < 4) {
        int r2 = blockIdx.x * 4 + threadIdx.x;
        float v = part[2 * threadIdx.x] + part[2 * threadIdx.x + 1] + comb_b[r2];
        g_x0[r2] = fmaxf(v, 0.f);
    }
}

// ---------------- K3: ih-side cell-0 gates + ticket-fused combine ----------
// 3072 warps / 384 blocks; last block out computes h1, x1.
__global__ void __launch_bounds__(256)
k_gates0(const float* __restrict__ w_ih,
         const float* __restrict__ b_ih, const float* __restrict__ b_hh,
         const float* __restrict__ hidden) {
    __shared__ unsigned s_tick;
    int warp = threadIdx.x >> 5, lane = threadIdx.x & 31;
    int gw = blockIdx.x * 8 + warp;           // 0..3071
    int gate = gw >> 10, i = gw & (H - 1);
    const float4* wf = (const float4*)(w_ih + (size_t)(gate * H + i) * H);
    const float4* vf = (const float4*)g_x0;
    float acc = 0.f;
    #pragma unroll
    for (int k = 0; k < 8; k++) acc += dot4(wf[lane + k * 32], vf[lane + k * 32]);
    acc = wred(acc);
    if (lane == 0) g_dp[(2 * gate) * H + i] = acc;

    __threadfence();
    __syncthreads();
    if (threadIdx.x == 0) s_tick = atomicAdd(&g_t0, 1u);
    __syncthreads();
    if (s_tick == gridDim.x - 1) {
        for (int i2 = threadIdx.x; i2 < H; i2 += 256) {
            float d0 = __ldcg(&g_dp[0 * H + i2]) + b_ih[i2];
            float d1 = __ldcg(&g_dp[1 * H + i2]) + b_hh[i2];
            float d2 = __ldcg(&g_dp[2 * H + i2]) + b_ih[H + i2];
            float d3 = __ldcg(&g_dp[3 * H + i2]) + b_hh[H + i2];
            float d4 = __ldcg(&g_dp[4 * H + i2]) + b_ih[2 * H + i2];
            float d5 = __ldcg(&g_dp[5 * H + i2]) + b_hh[2 * H + i2];
            float h = gru_elem(d0, d1, d2, d3, d4, d5, hidden[i2]);
            g_h1[i2] = h;
            g_x1[i2] = fmaxf(h, 0.f);
        }
    }
}

// ---------------- K4: cell-1 gates (both matrices, L2-hot) + combine -------
// 6144 warps / 768 blocks; last block out computes h2 + hidden output.
__global__ void __launch_bounds__(256)
k_gates1(const float* __restrict__ w_ih, const float* __restrict__ w_hh,
         const float* __restrict__ b_ih, const float* __restrict__ b_hh,
         float* __restrict__ out) {
    __shared__ unsigned s_tick;
    int warp = threadIdx.x >> 5, lane = threadIdx.x & 31;
    int u = blockIdx.x * 8 + warp;            // 0..6143
    int c = u >> 10, i = u & (H - 1);
    int gate = c >> 1;
    const float* wm = (c & 1) ? w_hh : w_ih;
    const float4* wf = (const float4*)(wm + (size_t)(gate * H + i) * H);
    const float4* vf = (const float4*)((c & 1) ? g_h1 : g_x1);
    float acc = 0.f;
    #pragma unroll
    for (int k = 0; k < 8; k++) acc += dot4(wf[lane + k * 32], vf[lane + k * 32]);
    acc = wred(acc);
    if (lane == 0) g_dp[c * H + i] = acc;

    __threadfence();
    __syncthreads();
    if (threadIdx.x == 0) s_tick = atomicAdd(&g_t1, 1u);
    __syncthreads();
    if (s_tick == gridDim.x - 1) {
        for (int i2 = threadIdx.x; i2 < H; i2 += 256) {
            float d0 = __ldcg(&g_dp[0 * H + i2]) + b_ih[i2];
            float d1 = __ldcg(&g_dp[1 * H + i2]) + b_hh[i2];
            float d2 = __ldcg(&g_dp[2 * H + i2]) + b_ih[H + i2];
            float d3 = __ldcg(&g_dp[3 * H + i2]) + b_hh[H + i2];
            float d4 = __ldcg(&g_dp[4 * H + i2]) + b_ih[2 * H + i2];
            float d5 = __ldcg(&g_dp[5 * H + i2]) + b_hh[2 * H + i2];
            float h = gru_elem(d0, d1, d2, d3, d4, d5, g_h1[i2]);
            g_h2[i2] = h;
            out[V + i2] = h;
        }
    }
}

// ---------------- K5: big matvec out_w @ h2 + fused lse --------------------
__global__ void __launch_bounds__(256)
k_out(const float* __restrict__ out_w,
      const float* __restrict__ out_b,
      float* __restrict__ out) {
    __shared__ float sm[8];
    __shared__ unsigned s_tick;
    int warp = threadIdx.x >> 5, lane = threadIdx.x & 31;
    int row = blockIdx.x * 8 + warp;
    float logit = -1e30f;
    if (row < V) {
        const float4* w = (const float4*)(out_w + (size_t)row * H);
        const float4* v = (const float4*)g_h2;
        float acc = 0.f;
        #pragma unroll
        for (int k = 0; k < 8; k++) {
            int m = lane + k * 32;
            float4 a = __ldcs(w + m);   // stream weights
            float4 b = v[m];            // L1-resident vector
            acc += dot4(a, b);
        }
        acc = wred(acc);
        if (lane == 0) {
            logit = acc + out_b[row];
            out[row] = logit;
        }
    }
    if (lane == 0) sm[warp] = logit;
    __syncthreads();
    if (threadIdx.x == 0) {
        float m = -1e30f;
        #pragma unroll
        for (int k = 0; k < 8; k++) m = fmaxf(m, sm[k]);
        float s = 0.f;
        #pragma unroll
        for (int k = 0; k < 8; k++) s += __expf(sm[k] - m);
        g_pm[blockIdx.x] = m;
        g_ps[blockIdx.x] = s;
    }
    __threadfence();
    __syncthreads();
    if (threadIdx.x == 0) s_tick = atomicAdd(&g_t2, 1u);
    __syncthreads();
    if (s_tick == NBLK - 1) {
        int t = threadIdx.x;
        float m = -1e30f, s = 0.f;
        for (int b = t; b < NBLK; b += 256) {
            float bm = __ldcg(&g_pm[b]), bs = __ldcg(&g_ps[b]);
            if (bm > m) { s = s * __expf(m - bm) + bs; m = bm; }
            else        { s += bs * __expf(bm - m); }
        }
        __shared__ float rm[8], rs[8];
        #pragma unroll
        for (int o = 16; o; o >>= 1) {
            float om = __shfl_xor_sync(0xffffffffu, m, o);
            float os = __shfl_xor_sync(0xffffffffu, s, o);
            float M = fmaxf(m, om);
            s = s * __expf(m - M) + os * __expf(om - M);
            m = M;
        }
        if ((t & 31) == 0) { rm[t >> 5] = m; rs[t >> 5] = s; }
        __syncthreads();
        if (t < 8) {
            m = rm[t]; s = rs[t];
            #pragma unroll
            for (int o = 4; o; o >>= 1) {
                float om = __shfl_xor_sync(0xffu, m, o);
                float os = __shfl_xor_sync(0xffu, s, o);
                float M = fmaxf(m, om);
                s = s * __expf(m - M) + os * __expf(om - M);
                m = M;
            }
            if (t == 0) g_lse = m + logf(s);
        }
    }
}

// ---------------- K6: normalize log-probs ----------------------------------
__global__ void __launch_bounds__(256)
k_norm(float* __restrict__ out) {
    int v = blockIdx.x * blockDim.x + threadIdx.x;
    if (v < V) out[v] -= g_lse;
}

// ---------------- launch ----------------------------------------------------
extern "C" void kernel_launch(void* const* d_in, const int* in_sizes, int n_in,
                              void* d_out, int out_size) {
    const int*   ids     = (const int*)d_in[0];
    const float* hidden  = (const float*)d_in[1];
    const float* enc     = (const float*)d_in[2];
    const float* emb     = (const float*)d_in[3];
    const float* attn_w  = (const float*)d_in[4];
    const float* attn_b  = (const float*)d_in[5];
    const float* comb_w  = (const float*)d_in[6];
    const float* comb_b  = (const float*)d_in[7];
    const float* w_ih    = (const float*)d_in[8];
    const float* w_hh    = (const float*)d_in[9];
    const float* b_ih    = (const float*)d_in[10];
    const float* b_hh    = (const float*)d_in[11];
    const float* out_w   = (const float*)d_in[12];
    const float* out_b   = (const float*)d_in[13];
    float* out = (float*)d_out;

    k_reset<<<1, 32>>>();
    k_scores_hh<<<392, 256>>>(ids, hidden, emb, attn_w, attn_b, w_hh);
    k_attn<<<8, 128>>>(enc, out);
    k_comb<<<H / 4, 256>>>(comb_w, comb_b);
    k_gates0<<<384, 256>>>(w_ih, b_ih, b_hh, hidden);
    k_gates1<<<768, 256>>>(w_ih, w_hh, b_ih, b_hh, out);
    k_out<<<NBLK, 256>>>(out_w, out_b, out);
    k_norm<<<(V + 255) / 256, 256>>>(out);
}